// round 1
// baseline (speedup 1.0000x reference)
#include <cuda_runtime.h>
#include <math.h>

// Problem constants (fixed by reference: x = (4, 64, 128, 128) fp32)
#define HH 128
#define WW 128
#define BB 4

// Scratch (allocation-free: __device__ globals)
__device__ float g_A[BB * 128 * HH * WW];   // 32 MB ping
__device__ float g_B[BB * 128 * HH * WW];   // 32 MB pong
__device__ float g_off[BB * 18 * HH * WW];  // offsets
__device__ float g_wt[128 * 9 * 128];       // transposed deform weights [c*9+k][O]

__device__ __forceinline__ float lrelu(float v) { return v >= 0.f ? v : 0.2f * v; }

// ---------------------------------------------------------------------------
// Plain 3x3 conv, stride 1, pad 1, optional LeakyReLU.
// Tile: 32(x) x 16(y) pixels, 8 output channels per block.
// 128 threads: thread = (lx 0..7, ly 0..15), computes 4 consecutive x pixels
// for 8 output channels -> 32 fp32 accumulators.
// ---------------------------------------------------------------------------
template<int CIN, bool RELU>
__global__ __launch_bounds__(128)
void conv3x3_kernel(const float* __restrict__ x, const float* __restrict__ w,
                    const float* __restrict__ bias, float* __restrict__ y,
                    int Cout, int n_ocb)
{
    __shared__ float w_s[8][CIN * 9];
    __shared__ float in_s[4][18][34];

    const int t   = threadIdx.x;
    const int lx  = t & 7;
    const int ly  = t >> 3;
    const int bx  = blockIdx.x * 32;
    const int by  = blockIdx.y * 16;
    const int b   = blockIdx.z / n_ocb;
    const int ocb = blockIdx.z % n_ocb;
    const int oc0 = ocb * 8;

    // Load this block's 8-channel weight slab (zero-fill beyond Cout)
    for (int i = t; i < 8 * CIN * 9; i += 128) {
        int oc = i / (CIN * 9);
        int j  = i - oc * (CIN * 9);
        w_s[oc][j] = (oc0 + oc < Cout) ? w[(oc0 + oc) * (CIN * 9) + j] : 0.f;
    }
    float bv[8];
    #pragma unroll
    for (int i = 0; i < 8; i++)
        bv[i] = (oc0 + i < Cout) ? bias[oc0 + i] : 0.f;

    float acc[8][4];
    #pragma unroll
    for (int i = 0; i < 8; i++)
        #pragma unroll
        for (int p = 0; p < 4; p++) acc[i][p] = 0.f;

    const float* xb = x + b * CIN * HH * WW;

    for (int c0 = 0; c0 < CIN; c0 += 4) {
        __syncthreads();
        // Load 4 input channels of a (16+2) x (32+2) halo tile
        for (int i = t; i < 4 * 18 * 34; i += 128) {
            int cc  = i / (18 * 34);
            int rem = i - cc * (18 * 34);
            int r   = rem / 34;
            int col = rem - r * 34;
            int gy  = by - 1 + r;
            int gx  = bx - 1 + col;
            float v = 0.f;
            if ((unsigned)gy < (unsigned)HH && (unsigned)gx < (unsigned)WW)
                v = xb[(c0 + cc) * HH * WW + gy * WW + gx];
            in_s[cc][r][col] = v;
        }
        __syncthreads();
        #pragma unroll
        for (int cc = 0; cc < 4; cc++) {
            float in[3][6];
            #pragma unroll
            for (int r = 0; r < 3; r++)
                #pragma unroll
                for (int cl = 0; cl < 6; cl++)
                    in[r][cl] = in_s[cc][ly + r][lx * 4 + cl];
            #pragma unroll
            for (int oc = 0; oc < 8; oc++) {
                float wr[9];
                #pragma unroll
                for (int j = 0; j < 9; j++) wr[j] = w_s[oc][(c0 + cc) * 9 + j];
                #pragma unroll
                for (int p = 0; p < 4; p++)
                    #pragma unroll
                    for (int ry = 0; ry < 3; ry++)
                        #pragma unroll
                        for (int rx = 0; rx < 3; rx++)
                            acc[oc][p] += in[ry][p + rx] * wr[ry * 3 + rx];
            }
        }
    }

    const int gy = by + ly;
    const int gx = bx + lx * 4;
    #pragma unroll
    for (int oc = 0; oc < 8; oc++) {
        if (oc0 + oc < Cout) {
            float v0 = acc[oc][0] + bv[oc];
            float v1 = acc[oc][1] + bv[oc];
            float v2 = acc[oc][2] + bv[oc];
            float v3 = acc[oc][3] + bv[oc];
            if (RELU) { v0 = lrelu(v0); v1 = lrelu(v1); v2 = lrelu(v2); v3 = lrelu(v3); }
            float4 r4 = make_float4(v0, v1, v2, v3);
            *(float4*)&y[((b * Cout + oc0 + oc) * HH + gy) * WW + gx] = r4;
        }
    }
}

// ---------------------------------------------------------------------------
// One-time weight transpose: wt[(c*9+k)*O + o] = w[o][c][ky][kx]
// ---------------------------------------------------------------------------
__global__ void wt_kernel(const float* __restrict__ w, float* __restrict__ wt,
                          int C9, int O)
{
    int idx = blockIdx.x * 256 + threadIdx.x;
    if (idx < O * C9) {
        int o = idx / C9;
        int j = idx - o * C9;
        wt[j * O + o] = w[idx];
    }
}

// ---------------------------------------------------------------------------
// Deformable 3x3 conv + LeakyReLU (torchvision semantics, no modulation).
// Block: 128 threads, 32 consecutive x pixels on one row, all O channels.
//   Phase 0: precompute 9 taps x 32 px: (y0, x0, wy, wx) to smem.
//   Loop over C in chunks of 16:
//     load transposed weight slab [144][O] (coalesced, conflict-free),
//     phase A: bilinear-sample val[cc][k][px] -> smem,
//     phase B: outer-product GEMM, thread = (og, pg): OT channels x 4 px.
// ---------------------------------------------------------------------------
template<int C, int O>
__global__ __launch_bounds__(128)
void dconv3x3_kernel(const float* __restrict__ x, const float* __restrict__ off,
                     const float* __restrict__ wt, const float* __restrict__ bias,
                     float* __restrict__ y)
{
    constexpr int CC = 16;
    constexpr int OT = O / 16;          // 8 (O=128) or 4 (O=64)
    extern __shared__ float dsm[];
    float* t_wy  = dsm;                  // 288
    float* t_wx  = dsm + 288;            // 288
    int*   t_y0  = (int*)(dsm + 576);    // 288
    int*   t_x0  = (int*)(dsm + 864);    // 288
    float* val_s = dsm + 1152;           // CC*9*32
    float* w_s   = dsm + 1152 + CC * 9 * 32;  // CC*9*O

    const int t  = threadIdx.x;
    const int og = t >> 3;               // 0..15
    const int pg = t & 7;                // 0..7  (px base = pg*4)
    const int x0 = blockIdx.x * 32;
    const int yy = blockIdx.y;
    const int b  = blockIdx.z;

    // Phase 0: taps
    for (int j = t; j < 288; j += 128) {
        int px = j & 31;
        int k  = j >> 5;
        int gx = x0 + px;
        float dy = off[((b * 18 + 2 * k) * HH + yy) * WW + gx];
        float dx = off[((b * 18 + 2 * k + 1) * HH + yy) * WW + gx];
        int ky = k / 3;
        int kx = k - ky * 3;
        float py  = (float)(yy + ky - 1) + dy;
        float pxx = (float)(gx + kx - 1) + dx;
        float fy = floorf(py), fx = floorf(pxx);
        t_y0[j] = (int)fy;
        t_x0[j] = (int)fx;
        t_wy[j] = py - fy;
        t_wx[j] = pxx - fx;
    }

    float acc[OT][4];
    #pragma unroll
    for (int i = 0; i < OT; i++)
        #pragma unroll
        for (int p = 0; p < 4; p++) acc[i][p] = 0.f;

    const float* xb = x + b * C * HH * WW;

    for (int c0 = 0; c0 < C; c0 += CC) {
        __syncthreads();  // taps ready (1st iter) / prior phase B done
        // load weight slab: wt rows [c0*9, c0*9 + CC*9), fully contiguous
        for (int i = t; i < CC * 9 * O; i += 128)
            w_s[i] = wt[c0 * 9 * O + i];
        // phase A: bilinear samples
        for (int j = t; j < CC * 9 * 32; j += 128) {
            int px = j & 31;
            int kj = j >> 5;             // cc*9 + k
            int cc = kj / 9;
            int k  = kj - cc * 9;
            int ti = k * 32 + px;
            int yi = t_y0[ti], xi = t_x0[ti];
            float wyv = t_wy[ti], wxv = t_wx[ti];
            const float* xc = xb + (c0 + cc) * HH * WW;
            float a00 = 0.f, a01 = 0.f, a10 = 0.f, a11 = 0.f;
            bool xin0 = (unsigned)xi < (unsigned)WW;
            bool xin1 = (unsigned)(xi + 1) < (unsigned)WW;
            if ((unsigned)yi < (unsigned)HH) {
                const float* row = xc + yi * WW;
                if (xin0) a00 = row[xi];
                if (xin1) a01 = row[xi + 1];
            }
            if ((unsigned)(yi + 1) < (unsigned)HH) {
                const float* row = xc + (yi + 1) * WW;
                if (xin0) a10 = row[xi];
                if (xin1) a11 = row[xi + 1];
            }
            float v0 = a00 + (a01 - a00) * wxv;
            float v1 = a10 + (a11 - a10) * wxv;
            val_s[j] = v0 + (v1 - v0) * wyv;
        }
        __syncthreads();
        // phase B: outer-product accumulate
        #pragma unroll 2
        for (int kk = 0; kk < CC * 9; kk++) {
            float4 v4 = *(const float4*)&val_s[kk * 32 + pg * 4];
            const float* wrow = &w_s[kk * O + og * OT];
            #pragma unroll
            for (int i4 = 0; i4 < OT; i4 += 4) {
                float4 w4 = *(const float4*)&wrow[i4];
                acc[i4 + 0][0] += w4.x * v4.x; acc[i4 + 0][1] += w4.x * v4.y;
                acc[i4 + 0][2] += w4.x * v4.z; acc[i4 + 0][3] += w4.x * v4.w;
                acc[i4 + 1][0] += w4.y * v4.x; acc[i4 + 1][1] += w4.y * v4.y;
                acc[i4 + 1][2] += w4.y * v4.z; acc[i4 + 1][3] += w4.y * v4.w;
                acc[i4 + 2][0] += w4.z * v4.x; acc[i4 + 2][1] += w4.z * v4.y;
                acc[i4 + 2][2] += w4.z * v4.z; acc[i4 + 2][3] += w4.z * v4.w;
                acc[i4 + 3][0] += w4.w * v4.x; acc[i4 + 3][1] += w4.w * v4.y;
                acc[i4 + 3][2] += w4.w * v4.z; acc[i4 + 3][3] += w4.w * v4.w;
            }
        }
    }

    const int gx = x0 + pg * 4;
    #pragma unroll
    for (int i = 0; i < OT; i++) {
        int o = og * OT + i;
        float bvv = bias[o];
        float4 r4;
        r4.x = lrelu(acc[i][0] + bvv);
        r4.y = lrelu(acc[i][1] + bvv);
        r4.z = lrelu(acc[i][2] + bvv);
        r4.w = lrelu(acc[i][3] + bvv);
        *(float4*)&y[((b * O + o) * HH + yy) * WW + gx] = r4;
    }
}

// ---------------------------------------------------------------------------
// Launch: 3 stages, each = conv(+leaky) -> offset conv -> weight transpose ->
// deformable conv(+leaky). All on default stream, graph-capturable.
// ---------------------------------------------------------------------------
extern "C" void kernel_launch(void* const* d_in, const int* in_sizes, int n_in,
                              void* d_out, int out_size)
{
    const float* x = (const float*)d_in[0];
    // per-stage params: cw, cb, ow, ob, dw, db
    const float* p[18];
    for (int i = 0; i < 18; i++) p[i] = (const float*)d_in[1 + i];

    float *A, *Bf, *OFF, *WT;
    cudaGetSymbolAddress((void**)&A,   g_A);
    cudaGetSymbolAddress((void**)&Bf,  g_B);
    cudaGetSymbolAddress((void**)&OFF, g_off);
    cudaGetSymbolAddress((void**)&WT,  g_wt);

    const int smem128 = (1152 + 16 * 9 * 32 + 16 * 9 * 128) * 4;  // 96768
    const int smem64  = (1152 + 16 * 9 * 32 + 16 * 9 * 64) * 4;   // 59904
    cudaFuncSetAttribute(dconv3x3_kernel<128, 128>,
                         cudaFuncAttributeMaxDynamicSharedMemorySize, smem128);
    cudaFuncSetAttribute(dconv3x3_kernel<64, 64>,
                         cudaFuncAttributeMaxDynamicSharedMemorySize, smem64);

    dim3 blk(128);
    dim3 dgrid(WW / 32, HH, BB);

    // ---- stage 1: 64 -> 128 ----
    conv3x3_kernel<64, true><<<dim3(4, 8, BB * 16), blk>>>(x, p[0], p[1], A, 128, 16);
    conv3x3_kernel<128, false><<<dim3(4, 8, BB * 3), blk>>>(A, p[2], p[3], OFF, 18, 3);
    wt_kernel<<<(128 * 9 * 128 + 255) / 256, 256>>>(p[4], WT, 128 * 9, 128);
    dconv3x3_kernel<128, 128><<<dgrid, blk, smem128>>>(A, OFF, WT, p[5], Bf);

    // ---- stage 2: 128 -> 128 ----
    conv3x3_kernel<128, true><<<dim3(4, 8, BB * 16), blk>>>(Bf, p[6], p[7], A, 128, 16);
    conv3x3_kernel<128, false><<<dim3(4, 8, BB * 3), blk>>>(A, p[8], p[9], OFF, 18, 3);
    wt_kernel<<<(128 * 9 * 128 + 255) / 256, 256>>>(p[10], WT, 128 * 9, 128);
    dconv3x3_kernel<128, 128><<<dgrid, blk, smem128>>>(A, OFF, WT, p[11], Bf);

    // ---- stage 3: 128 -> 64 ----
    conv3x3_kernel<128, true><<<dim3(4, 8, BB * 8), blk>>>(Bf, p[12], p[13], A, 64, 8);
    conv3x3_kernel<64, false><<<dim3(4, 8, BB * 3), blk>>>(A, p[14], p[15], OFF, 18, 3);
    wt_kernel<<<(64 * 9 * 64 + 255) / 256, 256>>>(p[16], WT, 64 * 9, 64);
    dconv3x3_kernel<64, 64><<<dgrid, blk, smem64>>>(A, OFF, WT, p[17], (float*)d_out);
}

// round 2
// speedup vs baseline: 1.4568x; 1.4568x over previous
#include <cuda_runtime.h>
#include <math.h>

// Problem constants (fixed by reference: x = (4, 64, 128, 128) fp32)
#define HH 128
#define WW 128
#define BB 4

// Scratch (allocation-free: __device__ globals)
__device__ float g_A[BB * 128 * HH * WW];   // 32 MB ping
__device__ float g_B[BB * 128 * HH * WW];   // 32 MB pong
__device__ float g_off[BB * 18 * HH * WW];  // offsets
__device__ float g_wtc[128 * 9 * 128];      // transposed conv weights  [cin*9][OP]
__device__ float g_wto[128 * 9 * 24];       // transposed offset-conv weights (pad 24)
__device__ float g_wtd[128 * 9 * 128];      // transposed deform weights [c*9+k][O]

__device__ __forceinline__ float lrelu(float v) { return v >= 0.f ? v : 0.2f * v; }

// ---------------------------------------------------------------------------
// Weight transpose + pad: wt[j*OP + o] = (o < O) ? w[o*C9 + j] : 0
// ---------------------------------------------------------------------------
__global__ void wt_pad_kernel(const float* __restrict__ w, float* __restrict__ wt,
                              int C9, int O, int OP)
{
    int idx = blockIdx.x * 256 + threadIdx.x;
    if (idx < C9 * OP) {
        int j = idx / OP;
        int o = idx - j * OP;
        wt[idx] = (o < O) ? w[o * C9 + j] : 0.f;
    }
}

// ---------------------------------------------------------------------------
// Plain 3x3 conv, stride 1, pad 1, optional LeakyReLU.
// Tile: 32(x) x 16(y) pixels, 8 output channels per block, 128 threads.
// Weights pre-transposed to [cin*9][OP] so each tap is 2x LDS.128.
// ---------------------------------------------------------------------------
template<int CIN, bool RELU>
__global__ __launch_bounds__(128)
void conv3x3_kernel(const float* __restrict__ x, const float* __restrict__ wt,
                    const float* __restrict__ bias, float* __restrict__ y,
                    int Cout, int OP, int n_ocb)
{
    __shared__ float w_s[CIN * 9][8];
    __shared__ float in_s[4][18][34];

    const int t   = threadIdx.x;
    const int lx  = t & 7;
    const int ly  = t >> 3;
    const int bx  = blockIdx.x * 32;
    const int by  = blockIdx.y * 16;
    const int b   = blockIdx.z / n_ocb;
    const int ocb = blockIdx.z % n_ocb;
    const int oc0 = ocb * 8;

    // Load this block's 8-channel transposed weight slab (padded cols are 0)
    for (int i = t; i < CIN * 9 * 2; i += 128) {
        int row  = i >> 1;
        int half = i & 1;
        *(float4*)&w_s[row][half * 4] =
            *(const float4*)&wt[row * OP + oc0 + half * 4];
    }
    float bv[8];
    #pragma unroll
    for (int i = 0; i < 8; i++)
        bv[i] = (oc0 + i < Cout) ? bias[oc0 + i] : 0.f;

    float acc[8][4];
    #pragma unroll
    for (int i = 0; i < 8; i++)
        #pragma unroll
        for (int p = 0; p < 4; p++) acc[i][p] = 0.f;

    const float* xb = x + b * CIN * HH * WW;

    for (int c0 = 0; c0 < CIN; c0 += 4) {
        __syncthreads();
        // Load 4 input channels of a (16+2) x (32+2) halo tile
        for (int i = t; i < 4 * 18 * 34; i += 128) {
            int cc  = i / (18 * 34);
            int rem = i - cc * (18 * 34);
            int r   = rem / 34;
            int col = rem - r * 34;
            int gy  = by - 1 + r;
            int gx  = bx - 1 + col;
            float v = 0.f;
            if ((unsigned)gy < (unsigned)HH && (unsigned)gx < (unsigned)WW)
                v = xb[(c0 + cc) * HH * WW + gy * WW + gx];
            in_s[cc][r][col] = v;
        }
        __syncthreads();
        #pragma unroll
        for (int cc = 0; cc < 4; cc++) {
            float in[3][6];
            #pragma unroll
            for (int r = 0; r < 3; r++)
                #pragma unroll
                for (int cl = 0; cl < 6; cl++)
                    in[r][cl] = in_s[cc][ly + r][lx * 4 + cl];
            #pragma unroll
            for (int j = 0; j < 9; j++) {
                float4 wlo = *(float4*)&w_s[(c0 + cc) * 9 + j][0];
                float4 whi = *(float4*)&w_s[(c0 + cc) * 9 + j][4];
                int ry = j / 3, rx = j - ry * 3;
                #pragma unroll
                for (int p = 0; p < 4; p++) {
                    float iv = in[ry][p + rx];
                    acc[0][p] += iv * wlo.x;
                    acc[1][p] += iv * wlo.y;
                    acc[2][p] += iv * wlo.z;
                    acc[3][p] += iv * wlo.w;
                    acc[4][p] += iv * whi.x;
                    acc[5][p] += iv * whi.y;
                    acc[6][p] += iv * whi.z;
                    acc[7][p] += iv * whi.w;
                }
            }
        }
    }

    const int gy = by + ly;
    const int gx = bx + lx * 4;
    #pragma unroll
    for (int oc = 0; oc < 8; oc++) {
        if (oc0 + oc < Cout) {
            float v0 = acc[oc][0] + bv[oc];
            float v1 = acc[oc][1] + bv[oc];
            float v2 = acc[oc][2] + bv[oc];
            float v3 = acc[oc][3] + bv[oc];
            if (RELU) { v0 = lrelu(v0); v1 = lrelu(v1); v2 = lrelu(v2); v3 = lrelu(v3); }
            float4 r4 = make_float4(v0, v1, v2, v3);
            *(float4*)&y[((b * Cout + oc0 + oc) * HH + gy) * WW + gx] = r4;
        }
    }
}

// ---------------------------------------------------------------------------
// Deformable 3x3 conv + LeakyReLU (torchvision semantics, no modulation).
// Block: 256 threads, 64 consecutive x pixels on one row, all O channels.
// CC=8 channel chunks -> 63KB smem for O=128 -> 3 CTAs/SM (24 warps).
//   Phase 0: 9 taps x 64 px: (y0, x0, wy, wx) to smem.
//   Per chunk: load transposed weight slab [72][O], bilinear-sample
//   val[cc][k][px] -> smem, then outer-product GEMM:
//   thread = (og 0..15, pg 0..15): OT channels x 4 px.
// ---------------------------------------------------------------------------
template<int C, int O>
__global__ __launch_bounds__(256)
void dconv3x3_kernel(const float* __restrict__ x, const float* __restrict__ off,
                     const float* __restrict__ wt, const float* __restrict__ bias,
                     float* __restrict__ y)
{
    constexpr int CC = 8;
    constexpr int PX = 64;
    constexpr int OT = O / 16;          // 8 (O=128) or 4 (O=64)
    extern __shared__ float dsm[];
    float* t_wy  = dsm;                      // 576
    float* t_wx  = dsm + 576;                // 576
    int*   t_y0  = (int*)(dsm + 1152);       // 576
    int*   t_x0  = (int*)(dsm + 1728);       // 576
    float* val_s = dsm + 2304;               // CC*9*PX = 4608
    float* w_s   = dsm + 2304 + CC * 9 * PX; // CC*9*O

    const int t  = threadIdx.x;
    const int og = t >> 4;               // 0..15
    const int pg = t & 15;               // 0..15 (px base = pg*4)
    const int x0 = blockIdx.x * PX;
    const int yy = blockIdx.y;
    const int b  = blockIdx.z;

    // Phase 0: taps (px innermost -> coalesced offset reads)
    for (int j = t; j < 9 * PX; j += 256) {
        int px = j & (PX - 1);
        int k  = j >> 6;
        int gx = x0 + px;
        float dy = off[((b * 18 + 2 * k) * HH + yy) * WW + gx];
        float dx = off[((b * 18 + 2 * k + 1) * HH + yy) * WW + gx];
        int ky = k / 3;
        int kx = k - ky * 3;
        float py  = (float)(yy + ky - 1) + dy;
        float pxx = (float)(gx + kx - 1) + dx;
        float fy = floorf(py), fx = floorf(pxx);
        t_y0[j] = (int)fy;
        t_x0[j] = (int)fx;
        t_wy[j] = py - fy;
        t_wx[j] = pxx - fx;
    }

    float acc[OT][4];
    #pragma unroll
    for (int i = 0; i < OT; i++)
        #pragma unroll
        for (int p = 0; p < 4; p++) acc[i][p] = 0.f;

    const float* xb = x + b * C * HH * WW;

    for (int c0 = 0; c0 < C; c0 += CC) {
        __syncthreads();  // taps ready (1st iter) / prior phase B done
        // weight slab: rows [c0*9, c0*9 + CC*9) of wt, fully contiguous
        for (int i = t; i < CC * 9 * O / 4; i += 256)
            ((float4*)w_s)[i] = ((const float4*)(wt + c0 * 9 * O))[i];
        // phase A: bilinear samples (px innermost -> coalesced gathers)
        for (int j = t; j < CC * 9 * PX; j += 256) {
            int px = j & (PX - 1);
            int kj = j >> 6;             // cc*9 + k
            int cc = kj / 9;
            int k  = kj - cc * 9;
            int ti = k * PX + px;
            int yi = t_y0[ti], xi = t_x0[ti];
            float wyv = t_wy[ti], wxv = t_wx[ti];
            const float* xc = xb + (c0 + cc) * HH * WW;
            float a00 = 0.f, a01 = 0.f, a10 = 0.f, a11 = 0.f;
            bool xin0 = (unsigned)xi < (unsigned)WW;
            bool xin1 = (unsigned)(xi + 1) < (unsigned)WW;
            if ((unsigned)yi < (unsigned)HH) {
                const float* row = xc + yi * WW;
                if (xin0) a00 = row[xi];
                if (xin1) a01 = row[xi + 1];
            }
            if ((unsigned)(yi + 1) < (unsigned)HH) {
                const float* row = xc + (yi + 1) * WW;
                if (xin0) a10 = row[xi];
                if (xin1) a11 = row[xi + 1];
            }
            float v0 = a00 + (a01 - a00) * wxv;
            float v1 = a10 + (a11 - a10) * wxv;
            val_s[j] = v0 + (v1 - v0) * wyv;
        }
        __syncthreads();
        // phase B: outer-product accumulate
        #pragma unroll 4
        for (int kk = 0; kk < CC * 9; kk++) {
            float4 v4 = *(const float4*)&val_s[kk * PX + pg * 4];
            const float* wrow = &w_s[kk * O + og * OT];
            #pragma unroll
            for (int i4 = 0; i4 < OT; i4 += 4) {
                float4 w4 = *(const float4*)&wrow[i4];
                acc[i4 + 0][0] += w4.x * v4.x; acc[i4 + 0][1] += w4.x * v4.y;
                acc[i4 + 0][2] += w4.x * v4.z; acc[i4 + 0][3] += w4.x * v4.w;
                acc[i4 + 1][0] += w4.y * v4.x; acc[i4 + 1][1] += w4.y * v4.y;
                acc[i4 + 1][2] += w4.y * v4.z; acc[i4 + 1][3] += w4.y * v4.w;
                acc[i4 + 2][0] += w4.z * v4.x; acc[i4 + 2][1] += w4.z * v4.y;
                acc[i4 + 2][2] += w4.z * v4.z; acc[i4 + 2][3] += w4.z * v4.w;
                acc[i4 + 3][0] += w4.w * v4.x; acc[i4 + 3][1] += w4.w * v4.y;
                acc[i4 + 3][2] += w4.w * v4.z; acc[i4 + 3][3] += w4.w * v4.w;
            }
        }
    }

    const int gx = x0 + pg * 4;
    #pragma unroll
    for (int i = 0; i < OT; i++) {
        int o = og * OT + i;
        float bvv = bias[o];
        float4 r4;
        r4.x = lrelu(acc[i][0] + bvv);
        r4.y = lrelu(acc[i][1] + bvv);
        r4.z = lrelu(acc[i][2] + bvv);
        r4.w = lrelu(acc[i][3] + bvv);
        *(float4*)&y[((b * O + o) * HH + yy) * WW + gx] = r4;
    }
}

// ---------------------------------------------------------------------------
// Launch: 3 stages of conv(+leaky) -> offset conv -> deform conv(+leaky),
// each preceded by its weight transposes. Default stream, graph-capturable.
// ---------------------------------------------------------------------------
extern "C" void kernel_launch(void* const* d_in, const int* in_sizes, int n_in,
                              void* d_out, int out_size)
{
    const float* x = (const float*)d_in[0];
    const float* p[18];
    for (int i = 0; i < 18; i++) p[i] = (const float*)d_in[1 + i];

    float *A, *Bf, *OFF, *WTC, *WTO, *WTD;
    cudaGetSymbolAddress((void**)&A,   g_A);
    cudaGetSymbolAddress((void**)&Bf,  g_B);
    cudaGetSymbolAddress((void**)&OFF, g_off);
    cudaGetSymbolAddress((void**)&WTC, g_wtc);
    cudaGetSymbolAddress((void**)&WTO, g_wto);
    cudaGetSymbolAddress((void**)&WTD, g_wtd);

    const int smemD128 = (2304 + 8 * 9 * 64 + 8 * 9 * 128) * 4;  // 64512
    const int smemD64  = (2304 + 8 * 9 * 64 + 8 * 9 * 64) * 4;   // 46080
    cudaFuncSetAttribute(dconv3x3_kernel<128, 128>,
                         cudaFuncAttributeMaxDynamicSharedMemorySize, smemD128);
    cudaFuncSetAttribute(dconv3x3_kernel<64, 64>,
                         cudaFuncAttributeMaxDynamicSharedMemorySize, smemD64);

    dim3 blk128(128), blk256(256);
    dim3 dgrid(WW / 64, HH, BB);

    #define WTP(src, dst, C9, O, OP) \
        wt_pad_kernel<<<((C9) * (OP) + 255) / 256, 256>>>(src, dst, C9, O, OP)

    // ---- stage 1: 64 -> 128 ----
    WTP(p[0], WTC, 64 * 9, 128, 128);
    WTP(p[2], WTO, 128 * 9, 18, 24);
    WTP(p[4], WTD, 128 * 9, 128, 128);
    conv3x3_kernel<64, true><<<dim3(4, 8, BB * 16), blk128>>>(x, WTC, p[1], A, 128, 128, 16);
    conv3x3_kernel<128, false><<<dim3(4, 8, BB * 3), blk128>>>(A, WTO, p[3], OFF, 18, 24, 3);
    dconv3x3_kernel<128, 128><<<dgrid, blk256, smemD128>>>(A, OFF, WTD, p[5], Bf);

    // ---- stage 2: 128 -> 128 ----
    WTP(p[6], WTC, 128 * 9, 128, 128);
    WTP(p[8], WTO, 128 * 9, 18, 24);
    WTP(p[10], WTD, 128 * 9, 128, 128);
    conv3x3_kernel<128, true><<<dim3(4, 8, BB * 16), blk128>>>(Bf, WTC, p[7], A, 128, 128, 16);
    conv3x3_kernel<128, false><<<dim3(4, 8, BB * 3), blk128>>>(A, WTO, p[9], OFF, 18, 24, 3);
    dconv3x3_kernel<128, 128><<<dgrid, blk256, smemD128>>>(A, OFF, WTD, p[11], Bf);

    // ---- stage 3: 128 -> 64 ----
    WTP(p[12], WTC, 128 * 9, 64, 64);
    WTP(p[14], WTO, 64 * 9, 18, 24);
    WTP(p[16], WTD, 64 * 9, 64, 64);
    conv3x3_kernel<128, true><<<dim3(4, 8, BB * 8), blk128>>>(Bf, WTC, p[13], A, 64, 64, 8);
    conv3x3_kernel<64, false><<<dim3(4, 8, BB * 3), blk128>>>(A, WTO, p[15], OFF, 18, 24, 3);
    dconv3x3_kernel<64, 64><<<dgrid, blk256, smemD64>>>(A, OFF, WTD, p[17], (float*)d_out);

    #undef WTP
}